// round 1
// baseline (speedup 1.0000x reference)
#include <cuda_runtime.h>
#include <math.h>

// Problem constants (fixed shapes from reference)
#define BB   8
#define SS   1024
#define DD   1024
#define EE   8
#define FF   2048
#define KTOK 256   // tokens per expert = S*2/E

// ---------------- scratch (device globals; no allocation allowed) ----------
__device__ float g_probs[(size_t)BB * EE * SS];          // [b][e][s]
__device__ float g_G[(size_t)BB * EE * KTOK];            // gates
__device__ int   g_I[(size_t)BB * EE * KTOK];            // token indices
__device__ float g_h[(size_t)BB * EE * KTOK * FF];       // 128 MB intermediate

// ---------------- router: logits + softmax -> probs_t [b][e][s] ------------
__global__ __launch_bounds__(256) void router_kernel(const float* __restrict__ x,
                                                     const float* __restrict__ cw) {
    const int token = blockIdx.x;          // b*S + s
    const int b = token >> 10;
    const int s = token & (SS - 1);
    const float* xr = x + (size_t)token * DD;

    float acc[EE];
#pragma unroll
    for (int e = 0; e < EE; e++) acc[e] = 0.f;
    for (int d = threadIdx.x; d < DD; d += 256) {
        float xv = xr[d];
#pragma unroll
        for (int e = 0; e < EE; e++) acc[e] += xv * cw[e * DD + d];
    }

    __shared__ float sred[256];
    __shared__ float slogit[EE];
#pragma unroll
    for (int e = 0; e < EE; e++) {
        sred[threadIdx.x] = acc[e];
        __syncthreads();
        for (int off = 128; off > 0; off >>= 1) {
            if (threadIdx.x < off) sred[threadIdx.x] += sred[threadIdx.x + off];
            __syncthreads();
        }
        if (threadIdx.x == 0) slogit[e] = sred[0];
        __syncthreads();
    }
    if (threadIdx.x == 0) {
        float m = slogit[0];
#pragma unroll
        for (int e = 1; e < EE; e++) m = fmaxf(m, slogit[e]);
        float p[EE], sum = 0.f;
#pragma unroll
        for (int e = 0; e < EE; e++) { p[e] = expf(slogit[e] - m); sum += p[e]; }
        float inv = 1.f / sum;
#pragma unroll
        for (int e = 0; e < EE; e++)
            g_probs[((size_t)(b * EE + e)) * SS + s] = p[e] * inv;
    }
}

// ---------------- top-k per (b,e): bitonic sort of 1024 (val,idx) ----------
__global__ __launch_bounds__(512) void topk_kernel() {
    const int be = blockIdx.x;
    __shared__ float v[SS];
    __shared__ int   ix[SS];
    for (int i = threadIdx.x; i < SS; i += 512) {
        v[i]  = g_probs[(size_t)be * SS + i];
        ix[i] = i;
    }
    __syncthreads();
    // full descending sort; ties: lower index first (matches jax.lax.top_k)
    for (int ksz = 2; ksz <= SS; ksz <<= 1) {
        for (int j = ksz >> 1; j > 0; j >>= 1) {
            const int t = threadIdx.x;                    // exactly 512 pairs
            const int i = ((t & ~(j - 1)) << 1) | (t & (j - 1));
            const int p = i | j;
            const bool up = ((i & ksz) == 0);
            float vi = v[i], vp = v[p];
            int   xi = ix[i], xp = ix[p];
            bool i_better = (vi > vp) || (vi == vp && xi < xp);
            bool do_swap = up ? (!i_better) : i_better;
            if (do_swap) { v[i] = vp; v[p] = vi; ix[i] = xp; ix[p] = xi; }
            __syncthreads();
        }
    }
    for (int i = threadIdx.x; i < KTOK; i += 512) {
        g_G[(size_t)be * KTOK + i] = v[i];
        g_I[(size_t)be * KTOK + i] = ix[i];
    }
}

// ---------------- SGEMM tiles --------------------------------------------
#define BM 128
#define BN 128
#define BKK 8
#define TM 8
#define TN 8

// GEMM1: C[r, f] = silu( sum_d x[b, I[r], d] * w1[e, d, f] )  -> g_h
__global__ __launch_bounds__(256) void gemm1_kernel(const float* __restrict__ x,
                                                    const float* __restrict__ w1) {
    const int be = blockIdx.z;
    const int b = be >> 3, e = be & 7;
    const int rowTile = blockIdx.y * BM;
    const int colTile = blockIdx.x * BN;

    __shared__ float As[2][BKK][BM];
    __shared__ float Bs[2][BKK][BN];
    __shared__ int rowsm[BM];

    const int tid = threadIdx.x;
    if (tid < BM) rowsm[tid] = g_I[(size_t)be * KTOK + rowTile + tid];
    __syncthreads();

    const int arow = tid >> 1, acol = (tid & 1) << 2;
    const int brow = tid >> 5, bcol = (tid & 31) << 2;
    const float* aptr = x + ((size_t)(b * SS + rowsm[arow])) * DD + acol;
    const float* bptr = w1 + (size_t)e * DD * FF + (size_t)brow * FF + colTile + bcol;

    float4 al = *(const float4*)aptr;
    float4 bl = *(const float4*)bptr;
    As[0][acol + 0][arow] = al.x; As[0][acol + 1][arow] = al.y;
    As[0][acol + 2][arow] = al.z; As[0][acol + 3][arow] = al.w;
    *(float4*)&Bs[0][brow][bcol] = bl;
    __syncthreads();

    float acc[TM][TN];
#pragma unroll
    for (int i = 0; i < TM; i++)
#pragma unroll
        for (int j = 0; j < TN; j++) acc[i][j] = 0.f;

    const int ty = tid >> 4, tx = tid & 15;
    const int KT = DD / BKK;
    for (int kt = 0; kt < KT; kt++) {
        const int cb = kt & 1;
        if (kt + 1 < KT) {
            al = *(const float4*)(aptr + (kt + 1) * BKK);
            bl = *(const float4*)(bptr + (size_t)(kt + 1) * BKK * FF);
        }
#pragma unroll
        for (int kk = 0; kk < BKK; kk++) {
            float4 a0 = *(const float4*)&As[cb][kk][ty * TM];
            float4 a1 = *(const float4*)&As[cb][kk][ty * TM + 4];
            float4 b0 = *(const float4*)&Bs[cb][kk][tx * TN];
            float4 b1 = *(const float4*)&Bs[cb][kk][tx * TN + 4];
            float a[TM]  = {a0.x, a0.y, a0.z, a0.w, a1.x, a1.y, a1.z, a1.w};
            float bb[TN] = {b0.x, b0.y, b0.z, b0.w, b1.x, b1.y, b1.z, b1.w};
#pragma unroll
            for (int i = 0; i < TM; i++)
#pragma unroll
                for (int j = 0; j < TN; j++) acc[i][j] += a[i] * bb[j];
        }
        if (kt + 1 < KT) {
            const int nb = cb ^ 1;
            As[nb][acol + 0][arow] = al.x; As[nb][acol + 1][arow] = al.y;
            As[nb][acol + 2][arow] = al.z; As[nb][acol + 3][arow] = al.w;
            *(float4*)&Bs[nb][brow][bcol] = bl;
            __syncthreads();
        }
    }

#pragma unroll
    for (int i = 0; i < TM; i++) {
        const int r = rowTile + ty * TM + i;
        float* hp = g_h + ((size_t)be * KTOK + r) * FF + colTile + tx * TN;
#pragma unroll
        for (int j = 0; j < TN; j += 4) {
            float4 o;
            o.x = acc[i][j + 0] / (1.f + __expf(-acc[i][j + 0]));
            o.y = acc[i][j + 1] / (1.f + __expf(-acc[i][j + 1]));
            o.z = acc[i][j + 2] / (1.f + __expf(-acc[i][j + 2]));
            o.w = acc[i][j + 3] / (1.f + __expf(-acc[i][j + 3]));
            *(float4*)&hp[j] = o;
        }
    }
}

// GEMM2: out[b, I[r], d] += G[r] * sum_f h[r, f] * w2[e, f, d]
__global__ __launch_bounds__(256) void gemm2_kernel(const float* __restrict__ w2,
                                                    float* __restrict__ out) {
    const int be = blockIdx.z;
    const int b = be >> 3, e = be & 7;
    const int rowTile = blockIdx.y * BM;
    const int colTile = blockIdx.x * BN;

    __shared__ float As[2][BKK][BM];
    __shared__ float Bs[2][BKK][BN];
    __shared__ int rowsm[BM];

    const int tid = threadIdx.x;
    if (tid < BM) rowsm[tid] = g_I[(size_t)be * KTOK + rowTile + tid];
    __syncthreads();

    const int arow = tid >> 1, acol = (tid & 1) << 2;
    const int brow = tid >> 5, bcol = (tid & 31) << 2;
    const float* aptr = g_h + ((size_t)be * KTOK + rowTile + arow) * FF + acol;
    const float* bptr = w2 + (size_t)e * FF * DD + (size_t)brow * DD + colTile + bcol;

    float4 al = *(const float4*)aptr;
    float4 bl = *(const float4*)bptr;
    As[0][acol + 0][arow] = al.x; As[0][acol + 1][arow] = al.y;
    As[0][acol + 2][arow] = al.z; As[0][acol + 3][arow] = al.w;
    *(float4*)&Bs[0][brow][bcol] = bl;
    __syncthreads();

    float acc[TM][TN];
#pragma unroll
    for (int i = 0; i < TM; i++)
#pragma unroll
        for (int j = 0; j < TN; j++) acc[i][j] = 0.f;

    const int ty = tid >> 4, tx = tid & 15;
    const int KT = FF / BKK;
    for (int kt = 0; kt < KT; kt++) {
        const int cb = kt & 1;
        if (kt + 1 < KT) {
            al = *(const float4*)(aptr + (kt + 1) * BKK);
            bl = *(const float4*)(bptr + (size_t)(kt + 1) * BKK * DD);
        }
#pragma unroll
        for (int kk = 0; kk < BKK; kk++) {
            float4 a0 = *(const float4*)&As[cb][kk][ty * TM];
            float4 a1 = *(const float4*)&As[cb][kk][ty * TM + 4];
            float4 b0 = *(const float4*)&Bs[cb][kk][tx * TN];
            float4 b1 = *(const float4*)&Bs[cb][kk][tx * TN + 4];
            float a[TM]  = {a0.x, a0.y, a0.z, a0.w, a1.x, a1.y, a1.z, a1.w};
            float bb[TN] = {b0.x, b0.y, b0.z, b0.w, b1.x, b1.y, b1.z, b1.w};
#pragma unroll
            for (int i = 0; i < TM; i++)
#pragma unroll
                for (int j = 0; j < TN; j++) acc[i][j] += a[i] * bb[j];
        }
        if (kt + 1 < KT) {
            const int nb = cb ^ 1;
            As[nb][acol + 0][arow] = al.x; As[nb][acol + 1][arow] = al.y;
            As[nb][acol + 2][arow] = al.z; As[nb][acol + 3][arow] = al.w;
            *(float4*)&Bs[nb][brow][bcol] = bl;
            __syncthreads();
        }
    }

    // gated atomic scatter-add (tokens overlap across experts -> atomics)
#pragma unroll
    for (int i = 0; i < TM; i++) {
        const int r = rowTile + ty * TM + i;
        const int tok = rowsm[ty * TM + i];
        const float gate = g_G[(size_t)be * KTOK + r];
        float* op = out + ((size_t)b * SS + tok) * DD + colTile + tx * TN;
#pragma unroll
        for (int j = 0; j < TN; j++) {
            atomicAdd(&op[j], gate * acc[i][j]);
        }
    }
}

// ---------------- launcher -------------------------------------------------
extern "C" void kernel_launch(void* const* d_in, const int* in_sizes, int n_in,
                              void* d_out, int out_size) {
    const float* x  = (const float*)d_in[0];
    const float* cw = (const float*)d_in[1];
    const float* w1 = (const float*)d_in[2];
    const float* w2 = (const float*)d_in[3];
    float* out = (float*)d_out;

    cudaMemsetAsync(out, 0, (size_t)BB * SS * DD * sizeof(float), 0);

    router_kernel<<<BB * SS, 256>>>(x, cw);
    topk_kernel<<<BB * EE, 512>>>();

    dim3 g1(FF / BN, KTOK / BM, BB * EE);   // 16 x 2 x 64
    gemm1_kernel<<<g1, 256>>>(x, w1);

    dim3 g2(DD / BN, KTOK / BM, BB * EE);   // 8 x 2 x 64
    gemm2_kernel<<<g2, 256>>>(w2, out);
}

// round 3
// speedup vs baseline: 2.6331x; 2.6331x over previous
#include <cuda_runtime.h>
#include <cuda_bf16.h>
#include <cstdint>
#include <math.h>

// Shapes (fixed)
#define BB 8
#define SS 1024
#define DD 1024
#define EE 8
#define FF 2048
#define KTOK 256
#define NBE 64

// ---------------- fragment-major word-layout helpers ----------------
// A-type (M x K): word = ((mtile*KT + ktile)*4 + reg)*32 + lane
//   reg = ((m>>3)&1) + 2*((k>>3)&1), lane = (m&7)*4 + ((k&7)>>1), elem = k&1
//   mtile stride = KT*128 words
// B-type (N x K): word = ((ntile*KT + ktile)*2 + reg)*32 + lane
//   reg = (k>>3)&1, lane = (n&7)*4 + ((k&7)>>1), elem = k&1
//   ntile stride = KT*64 words

// ---------------- scratch (device globals; words = packed bf16x2) ----------
__device__ float g_probs[(size_t)NBE * SS];
__device__ float g_G[(size_t)NBE * KTOK];
__device__ int   g_I[(size_t)NBE * KTOK];
__device__ uint32_t g_xg_hi[(size_t)NBE * KTOK * DD / 2];   // A-type, KT=64
__device__ uint32_t g_xg_lo[(size_t)NBE * KTOK * DD / 2];
__device__ uint32_t g_h_hi[(size_t)NBE * KTOK * FF / 2];    // A-type, KT=128
__device__ uint32_t g_h_lo[(size_t)NBE * KTOK * FF / 2];
__device__ uint32_t g_w1t_hi[(size_t)EE * FF * DD / 2];     // B-type n=f,k=d, KT=64
__device__ uint32_t g_w1t_lo[(size_t)EE * FF * DD / 2];
__device__ uint32_t g_w2t_hi[(size_t)EE * DD * FF / 2];     // B-type n=d,k=f, KT=128
__device__ uint32_t g_w2t_lo[(size_t)EE * DD * FF / 2];

// ---------------- small helpers ----------------
__device__ __forceinline__ uint32_t smem_u32(const void* p) {
    uint32_t a;
    asm("{ .reg .u64 t; cvta.to.shared.u64 t, %1; cvt.u32.u64 %0, t; }" : "=r"(a) : "l"(p));
    return a;
}
#define CP16(dst_u32, gptr) \
    asm volatile("cp.async.cg.shared.global [%0], [%1], 16;" :: "r"(dst_u32), "l"(gptr))
#define CP_COMMIT() asm volatile("cp.async.commit_group;" ::: "memory")
#define CP_WAIT2()  asm volatile("cp.async.wait_group 2;" ::: "memory")

__device__ __forceinline__ void mma16816(float* d, const uint32_t* a, const uint32_t* b) {
    asm volatile(
        "mma.sync.aligned.m16n8k16.row.col.f32.bf16.bf16.f32 "
        "{%0,%1,%2,%3}, {%4,%5,%6,%7}, {%8,%9}, {%0,%1,%2,%3};"
        : "+f"(d[0]), "+f"(d[1]), "+f"(d[2]), "+f"(d[3])
        : "r"(a[0]), "r"(a[1]), "r"(a[2]), "r"(a[3]), "r"(b[0]), "r"(b[1]));
}

__device__ __forceinline__ void split_bf16(float v, __nv_bfloat16& hi, __nv_bfloat16& lo) {
    hi = __float2bfloat16_rn(v);
    lo = __float2bfloat16_rn(v - __bfloat162float(hi));
}
__device__ __forceinline__ uint32_t pack2(__nv_bfloat16 a, __nv_bfloat16 b) {
    __nv_bfloat162 p = __halves2bfloat162(a, b);
    return *(uint32_t*)&p;
}

// ---------------- router ----------------
__global__ __launch_bounds__(256) void router_kernel(const float* __restrict__ x,
                                                     const float* __restrict__ cw) {
    const int token = blockIdx.x;
    const int b = token >> 10;
    const int s = token & (SS - 1);
    const float* xr = x + (size_t)token * DD;
    float acc[EE];
#pragma unroll
    for (int e = 0; e < EE; e++) acc[e] = 0.f;
    for (int d = threadIdx.x; d < DD; d += 256) {
        float xv = xr[d];
#pragma unroll
        for (int e = 0; e < EE; e++) acc[e] += xv * cw[e * DD + d];
    }
    __shared__ float sred[256];
    __shared__ float slogit[EE];
#pragma unroll
    for (int e = 0; e < EE; e++) {
        sred[threadIdx.x] = acc[e];
        __syncthreads();
        for (int off = 128; off > 0; off >>= 1) {
            if (threadIdx.x < off) sred[threadIdx.x] += sred[threadIdx.x + off];
            __syncthreads();
        }
        if (threadIdx.x == 0) slogit[e] = sred[0];
        __syncthreads();
    }
    if (threadIdx.x == 0) {
        float m = slogit[0];
#pragma unroll
        for (int e = 1; e < EE; e++) m = fmaxf(m, slogit[e]);
        float p[EE], sum = 0.f;
#pragma unroll
        for (int e = 0; e < EE; e++) { p[e] = expf(slogit[e] - m); sum += p[e]; }
        float inv = 1.f / sum;
#pragma unroll
        for (int e = 0; e < EE; e++)
            g_probs[((size_t)(b * EE + e)) * SS + s] = p[e] * inv;
    }
}

// ---------------- top-k (bitonic full sort of 1024) ----------------
__global__ __launch_bounds__(512) void topk_kernel() {
    const int be = blockIdx.x;
    __shared__ float v[SS];
    __shared__ int   ix[SS];
    for (int i = threadIdx.x; i < SS; i += 512) {
        v[i]  = g_probs[(size_t)be * SS + i];
        ix[i] = i;
    }
    __syncthreads();
    for (int ksz = 2; ksz <= SS; ksz <<= 1) {
        for (int j = ksz >> 1; j > 0; j >>= 1) {
            const int t = threadIdx.x;
            const int i = ((t & ~(j - 1)) << 1) | (t & (j - 1));
            const int p = i | j;
            const bool up = ((i & ksz) == 0);
            float vi = v[i], vp = v[p];
            int   xi = ix[i], xp = ix[p];
            bool i_better = (vi > vp) || (vi == vp && xi < xp);
            bool do_swap = up ? (!i_better) : i_better;
            if (do_swap) { v[i] = vp; v[p] = vi; ix[i] = xp; ix[p] = xi; }
            __syncthreads();
        }
    }
    for (int i = threadIdx.x; i < KTOK; i += 512) {
        g_G[(size_t)be * KTOK + i] = v[i];
        g_I[(size_t)be * KTOK + i] = ix[i];
    }
}

// ---------------- weight conversion to fragment-major B-type ----------------
// w1[e][d][f] -> g_w1t (n=f, k=d, KT=64, ntStride=64*64=4096 words)
__global__ __launch_bounds__(256) void convw1_kernel(const float* __restrict__ w1) {
    __shared__ float tile[32][33];
    const int e = blockIdx.z, d0 = blockIdx.y * 32, f0 = blockIdx.x * 32;
    const int tx = threadIdx.x, ty = threadIdx.y;
    const float* src = w1 + (size_t)e * DD * FF;
#pragma unroll
    for (int j = 0; j < 32; j += 8)
        tile[ty + j][tx] = src[(size_t)(d0 + ty + j) * FF + f0 + tx];
    __syncthreads();
    const size_t ebase = (size_t)e * (FF * DD / 2);
    const int tt = ty * 32 + tx;
#pragma unroll
    for (int it = 0; it < 2; it++) {
        int u = tt + it * 256;          // 0..511 = 32 f x 16 dpairs
        int fl = u >> 4, dp = u & 15;
        int n = f0 + fl;
        int k = d0 + 2 * dp;
        float v0 = tile[2 * dp][fl], v1 = tile[2 * dp + 1][fl];
        __nv_bfloat16 h0, l0, h1, l1;
        split_bf16(v0, h0, l0); split_bf16(v1, h1, l1);
        size_t w = ebase + (size_t)(n >> 3) * 4096 + (size_t)(k >> 4) * 64
                 + ((k >> 3) & 1) * 32 + (n & 7) * 4 + ((k & 7) >> 1);
        g_w1t_hi[w] = pack2(h0, h1);
        g_w1t_lo[w] = pack2(l0, l1);
    }
}

// w2[e][f][d] -> g_w2t (n=d, k=f, KT=128, ntStride=128*64=8192 words)
__global__ __launch_bounds__(256) void convw2_kernel(const float* __restrict__ w2) {
    __shared__ float tile[32][33];
    const int e = blockIdx.z, f0 = blockIdx.y * 32, d0 = blockIdx.x * 32;
    const int tx = threadIdx.x, ty = threadIdx.y;
    const float* src = w2 + (size_t)e * FF * DD;
#pragma unroll
    for (int j = 0; j < 32; j += 8)
        tile[ty + j][tx] = src[(size_t)(f0 + ty + j) * DD + d0 + tx];
    __syncthreads();
    const size_t ebase = (size_t)e * (DD * FF / 2);
    const int tt = ty * 32 + tx;
#pragma unroll
    for (int it = 0; it < 2; it++) {
        int u = tt + it * 256;          // 32 d x 16 fpairs
        int dl = u >> 4, fp = u & 15;
        int n = d0 + dl;
        int k = f0 + 2 * fp;
        float v0 = tile[2 * fp][dl], v1 = tile[2 * fp + 1][dl];
        __nv_bfloat16 h0, l0, h1, l1;
        split_bf16(v0, h0, l0); split_bf16(v1, h1, l1);
        size_t w = ebase + (size_t)(n >> 3) * 8192 + (size_t)(k >> 4) * 64
                 + ((k >> 3) & 1) * 32 + (n & 7) * 4 + ((k & 7) >> 1);
        g_w2t_hi[w] = pack2(h0, h1);
        g_w2t_lo[w] = pack2(l0, l1);
    }
}

// ---------------- gather routed x rows -> A-type fragment-major ------------
__global__ __launch_bounds__(256) void gatherx_kernel(const float* __restrict__ x) {
    const int berow = blockIdx.x;
    const int be = berow >> 8;
    const int m  = berow & 255;
    const int b  = be >> 3;
    const int tok = g_I[(size_t)be * KTOK + m];
    const float4* src = (const float4*)(x + ((size_t)b * SS + tok) * DD);
    float4 v = src[threadIdx.x];
    const size_t bbase = (size_t)be * (KTOK * DD / 2);
    const int mtile = m >> 4;
    const int regm = (m >> 3) & 1;
    const int lanebase = (m & 7) * 4;
#pragma unroll
    for (int p = 0; p < 2; p++) {
        int k = threadIdx.x * 4 + p * 2;   // even k of the pair
        float e0 = p ? v.z : v.x;
        float e1 = p ? v.w : v.y;
        __nv_bfloat16 h0, l0, h1, l1;
        split_bf16(e0, h0, l0); split_bf16(e1, h1, l1);
        size_t w = bbase + (size_t)mtile * 8192 + (size_t)(k >> 4) * 128
                 + (regm + 2 * ((k >> 3) & 1)) * 32 + lanebase + ((k & 7) >> 1);
        g_xg_hi[w] = pack2(h0, h1);
        g_xg_lo[w] = pack2(l0, l1);
    }
}

// ---------------- GEMM mainloop (shared) ----------------
// Stage layout (bytes): A_hi 0, A_lo 8192, B_hi 16384, B_lo 24576. Stage=32KB.
#define STAGE_BYTES 32768
#define SMEM_DYN (3 * STAGE_BYTES)

__device__ __forceinline__ void load_stage(
    uint32_t sm_stage_u32,
    const uint32_t* __restrict__ aHi, const uint32_t* __restrict__ aLo,
    const uint32_t* __restrict__ bHi, const uint32_t* __restrict__ bLo,
    size_t aW, size_t bW, int kt0, int mtStride, int ntStride, int tid)
{
#pragma unroll
    for (int i = 0; i < 2; i++) {
        int ci = tid + i * 256;
        int mtL = ci >> 6, ktL = (ci >> 5) & 1, sub = ci & 31;
        size_t gw = aW + (size_t)mtL * mtStride + (size_t)(kt0 + ktL) * 128 + sub * 4;
        uint32_t ds = sm_stage_u32 + ci * 16;
        CP16(ds,         (const char*)(aHi + gw));
        CP16(ds + 8192,  (const char*)(aLo + gw));
    }
#pragma unroll
    for (int i = 0; i < 2; i++) {
        int ci = tid + i * 256;
        int ntL = ci >> 5, ktL = (ci >> 4) & 1, sub = ci & 15;
        size_t gw = bW + (size_t)ntL * ntStride + (size_t)(kt0 + ktL) * 64 + sub * 4;
        uint32_t ds = sm_stage_u32 + 16384 + ci * 16;
        CP16(ds,         (const char*)(bHi + gw));
        CP16(ds + 8192,  (const char*)(bLo + gw));
    }
}

__device__ __forceinline__ void compute_stage(const char* sm_stage, int wm, int wn,
                                              int lane, float acc[2][8][4])
{
    const uint32_t* sAh = (const uint32_t*)sm_stage;
    const uint32_t* sAl = (const uint32_t*)(sm_stage + 8192);
    const uint32_t* sBh = (const uint32_t*)(sm_stage + 16384);
    const uint32_t* sBl = (const uint32_t*)(sm_stage + 24576);
#pragma unroll
    for (int kt = 0; kt < 2; kt++) {
        uint32_t Ah[2][4], Al[2][4];
#pragma unroll
        for (int mt = 0; mt < 2; mt++) {
            int blk = (((2 * wm + mt) * 2 + kt) * 4) * 32;
#pragma unroll
            for (int r = 0; r < 4; r++) {
                Ah[mt][r] = sAh[blk + r * 32 + lane];
                Al[mt][r] = sAl[blk + r * 32 + lane];
            }
        }
#pragma unroll
        for (int nt = 0; nt < 8; nt++) {
            int blk = (((wn * 8 + nt) * 2 + kt) * 2) * 32;
            uint32_t Bh[2] = { sBh[blk + lane], sBh[blk + 32 + lane] };
            uint32_t Bl[2] = { sBl[blk + lane], sBl[blk + 32 + lane] };
#pragma unroll
            for (int mt = 0; mt < 2; mt++) {
                mma16816(acc[mt][nt], Ah[mt], Bh);
                mma16816(acc[mt][nt], Ah[mt], Bl);
                mma16816(acc[mt][nt], Al[mt], Bh);
            }
        }
    }
}

__device__ __forceinline__ void gemm_mainloop(
    const uint32_t* aHi, const uint32_t* aLo, const uint32_t* bHi, const uint32_t* bLo,
    size_t aW, size_t bW, int NT, int mtStride, int ntStride,
    char* smem, int tid, int wm, int wn, int lane, float acc[2][8][4])
{
    uint32_t smu = smem_u32(smem);
    load_stage(smu, aHi, aLo, bHi, bLo, aW, bW, 0, mtStride, ntStride, tid);
    CP_COMMIT();
    load_stage(smu + STAGE_BYTES, aHi, aLo, bHi, bLo, aW, bW, 2, mtStride, ntStride, tid);
    CP_COMMIT();
    int buf = 0, nxt = 2;
    for (int s = 0; s < NT; s++) {
        if (s + 2 < NT)
            load_stage(smu + nxt * STAGE_BYTES, aHi, aLo, bHi, bLo, aW, bW,
                       (s + 2) * 2, mtStride, ntStride, tid);
        CP_COMMIT();
        CP_WAIT2();
        __syncthreads();
        compute_stage(smem + buf * STAGE_BYTES, wm, wn, lane, acc);
        __syncthreads();
        buf = (buf + 1) == 3 ? 0 : buf + 1;
        nxt = (nxt + 1) == 3 ? 0 : nxt + 1;
    }
}

// ---------------- GEMM1: xg @ w1t -> silu -> h (fragment-major) -------------
__global__ __launch_bounds__(256, 1) void gemm1_tc() {
    const int be = blockIdx.z, e = be & 7;
    const int rowTile = blockIdx.y * 128;
    const int colTile = blockIdx.x * 128;
    extern __shared__ char smem[];
    const int tid = threadIdx.x, warp = tid >> 5, lane = tid & 31;
    const int wm = warp >> 1, wn = warp & 1;

    const size_t aW = (size_t)be * (KTOK * DD / 2) + (size_t)(rowTile >> 4) * 8192;
    const size_t bW = (size_t)e * (FF * DD / 2) + (size_t)(colTile >> 3) * 4096;

    float acc[2][8][4];
#pragma unroll
    for (int i = 0; i < 2; i++)
#pragma unroll
        for (int j = 0; j < 8; j++)
#pragma unroll
            for (int r = 0; r < 4; r++) acc[i][j][r] = 0.f;

    gemm_mainloop(g_xg_hi, g_xg_lo, g_w1t_hi, g_w1t_lo, aW, bW,
                  DD / 32, 64 * 128, 64 * 64, smem, tid, wm, wn, lane, acc);

    // epilogue: silu + split -> h (A-type, KT=128)
    const size_t hBase = (size_t)be * (KTOK * FF / 2);
#pragma unroll
    for (int mt = 0; mt < 2; mt++) {
#pragma unroll
        for (int nt = 0; nt < 8; nt++) {
            int f = colTile + wn * 64 + nt * 8 + (lane & 3) * 2;
#pragma unroll
            for (int ph = 0; ph < 2; ph++) {
                int m = rowTile + wm * 32 + mt * 16 + (lane >> 2) + ph * 8;
                float v0 = acc[mt][nt][ph * 2 + 0];
                float v1 = acc[mt][nt][ph * 2 + 1];
                float s0 = v0 / (1.f + __expf(-v0));
                float s1 = v1 / (1.f + __expf(-v1));
                __nv_bfloat16 h0, l0, h1, l1;
                split_bf16(s0, h0, l0); split_bf16(s1, h1, l1);
                size_t w = hBase + (size_t)(m >> 4) * 16384 + (size_t)(f >> 4) * 128
                         + (((m >> 3) & 1) + 2 * ((f >> 3) & 1)) * 32 + lane;
                g_h_hi[w] = pack2(h0, h1);
                g_h_lo[w] = pack2(l0, l1);
            }
        }
    }
}

// ---------------- GEMM2: h @ w2t -> gated scatter-add into out --------------
__global__ __launch_bounds__(256, 1) void gemm2_tc(float* __restrict__ out) {
    const int be = blockIdx.z, e = be & 7, b = be >> 3;
    const int rowTile = blockIdx.y * 128;
    const int colTile = blockIdx.x * 128;
    extern __shared__ char smem[];
    const int tid = threadIdx.x, warp = tid >> 5, lane = tid & 31;
    const int wm = warp >> 1, wn = warp & 1;

    const size_t aW = (size_t)be * (KTOK * FF / 2) + (size_t)(rowTile >> 4) * 16384;
    const size_t bW = (size_t)e * (DD * FF / 2) + (size_t)(colTile >> 3) * 8192;

    float acc[2][8][4];
#pragma unroll
    for (int i = 0; i < 2; i++)
#pragma unroll
        for (int j = 0; j < 8; j++)
#pragma unroll
            for (int r = 0; r < 4; r++) acc[i][j][r] = 0.f;

    gemm_mainloop(g_h_hi, g_h_lo, g_w2t_hi, g_w2t_lo, aW, bW,
                  FF / 32, 128 * 128, 128 * 64, smem, tid, wm, wn, lane, acc);

    __shared__ int   s_tok[128];
    __shared__ float s_gate[128];
    if (tid < 128) {
        size_t idx = (size_t)be * KTOK + rowTile + tid;
        s_tok[tid]  = g_I[idx];
        s_gate[tid] = g_G[idx];
    }
    __syncthreads();

#pragma unroll
    for (int mt = 0; mt < 2; mt++) {
#pragma unroll
        for (int nt = 0; nt < 8; nt++) {
            int d = colTile + wn * 64 + nt * 8 + (lane & 3) * 2;
#pragma unroll
            for (int ph = 0; ph < 2; ph++) {
                int rloc = wm * 32 + mt * 16 + (lane >> 2) + ph * 8;
                int tok = s_tok[rloc];
                float gate = s_gate[rloc];
                float* op = out + ((size_t)b * SS + tok) * DD + d;
                atomicAdd(op,     gate * acc[mt][nt][ph * 2 + 0]);
                atomicAdd(op + 1, gate * acc[mt][nt][ph * 2 + 1]);
            }
        }
    }
}

// ---------------- launcher ----------------
extern "C" void kernel_launch(void* const* d_in, const int* in_sizes, int n_in,
                              void* d_out, int out_size) {
    const float* x  = (const float*)d_in[0];
    const float* cw = (const float*)d_in[1];
    const float* w1 = (const float*)d_in[2];
    const float* w2 = (const float*)d_in[3];
    float* out = (float*)d_out;

    cudaFuncSetAttribute(gemm1_tc, cudaFuncAttributeMaxDynamicSharedMemorySize, SMEM_DYN);
    cudaFuncSetAttribute(gemm2_tc, cudaFuncAttributeMaxDynamicSharedMemorySize, SMEM_DYN);

    cudaMemsetAsync(out, 0, (size_t)BB * SS * DD * sizeof(float), 0);

    router_kernel<<<BB * SS, 256>>>(x, cw);
    topk_kernel<<<NBE, 512>>>();

    convw1_kernel<<<dim3(FF / 32, DD / 32, EE), dim3(32, 8)>>>(w1);
    convw2_kernel<<<dim3(DD / 32, FF / 32, EE), dim3(32, 8)>>>(w2);
    gatherx_kernel<<<NBE * KTOK, 256>>>(x);

    gemm1_tc<<<dim3(FF / 128, KTOK / 128, NBE), 256, SMEM_DYN>>>();
    gemm2_tc<<<dim3(DD / 128, KTOK / 128, NBE), 256, SMEM_DYN>>>(out);
}

// round 4
// speedup vs baseline: 3.0456x; 1.1567x over previous
#include <cuda_runtime.h>
#include <cuda_bf16.h>
#include <cstdint>
#include <math.h>

// Shapes (fixed)
#define BB 8
#define SS 1024
#define DD 1024
#define EE 8
#define FF 2048
#define KTOK 256
#define NBE 64

// ---------------- fragment-major word layouts (reg-contiguous) -------------
// A-type (M x K, KT = K):
//   word = ((m>>4)*(KT>>4) + (k>>4))*128 + ((m&7)*4 + ((k&7)>>1))*4
//          + ((m>>3)&1) + 2*((k>>3)&1)            ; elem = k&1
//   -> per (mtile,ktile) a 512B block; each lane's 4 regs contiguous (LDS.128)
// B-type (N x K, KT = K):
//   word = ((n>>3)*(KT>>5) + (k>>5))*128 + ((n&7)*4 + ((k&7)>>1))*4
//          + ((k>>4)&1)*2 + ((k>>3)&1)            ; elem = k&1
//   -> per (ntile, kpair) a 512B block; lane quad = {kt0b0,kt0b1,kt1b0,kt1b1}

// ---------------- scratch ----------------
__device__ float g_probs[(size_t)NBE * SS];
__device__ float g_G[(size_t)NBE * KTOK];
__device__ int   g_I[(size_t)NBE * KTOK];
__device__ uint32_t g_xg_hi[(size_t)NBE * KTOK * DD / 2];
__device__ uint32_t g_xg_lo[(size_t)NBE * KTOK * DD / 2];
__device__ uint32_t g_h_hi[(size_t)NBE * KTOK * FF / 2];
__device__ uint32_t g_h_lo[(size_t)NBE * KTOK * FF / 2];
__device__ uint32_t g_w1t_hi[(size_t)EE * FF * DD / 2];
__device__ uint32_t g_w1t_lo[(size_t)EE * FF * DD / 2];
__device__ uint32_t g_w2t_hi[(size_t)EE * DD * FF / 2];
__device__ uint32_t g_w2t_lo[(size_t)EE * DD * FF / 2];

// ---------------- helpers ----------------
__device__ __forceinline__ uint32_t smem_u32(const void* p) {
    uint32_t a;
    asm("{ .reg .u64 t; cvta.to.shared.u64 t, %1; cvt.u32.u64 %0, t; }" : "=r"(a) : "l"(p));
    return a;
}
#define CP16(dst_u32, gptr) \
    asm volatile("cp.async.cg.shared.global [%0], [%1], 16;" :: "r"(dst_u32), "l"(gptr))
#define CP_COMMIT() asm volatile("cp.async.commit_group;" ::: "memory")

__device__ __forceinline__ void mma16816(float* d, const uint32_t* a, const uint32_t* b) {
    asm volatile(
        "mma.sync.aligned.m16n8k16.row.col.f32.bf16.bf16.f32 "
        "{%0,%1,%2,%3}, {%4,%5,%6,%7}, {%8,%9}, {%0,%1,%2,%3};"
        : "+f"(d[0]), "+f"(d[1]), "+f"(d[2]), "+f"(d[3])
        : "r"(a[0]), "r"(a[1]), "r"(a[2]), "r"(a[3]), "r"(b[0]), "r"(b[1]));
}

__device__ __forceinline__ void split_bf16(float v, __nv_bfloat16& hi, __nv_bfloat16& lo) {
    hi = __float2bfloat16_rn(v);
    lo = __float2bfloat16_rn(v - __bfloat162float(hi));
}
__device__ __forceinline__ uint32_t pack2(__nv_bfloat16 a, __nv_bfloat16 b) {
    __nv_bfloat162 p = __halves2bfloat162(a, b);
    return *(uint32_t*)&p;
}

// ---------------- router ----------------
__global__ __launch_bounds__(256) void router_kernel(const float* __restrict__ x,
                                                     const float* __restrict__ cw) {
    const int token = blockIdx.x;
    const int b = token >> 10;
    const int s = token & (SS - 1);
    const float* xr = x + (size_t)token * DD;
    float acc[EE];
#pragma unroll
    for (int e = 0; e < EE; e++) acc[e] = 0.f;
    for (int d = threadIdx.x; d < DD; d += 256) {
        float xv = xr[d];
#pragma unroll
        for (int e = 0; e < EE; e++) acc[e] += xv * cw[e * DD + d];
    }
    __shared__ float sred[256];
    __shared__ float slogit[EE];
#pragma unroll
    for (int e = 0; e < EE; e++) {
        sred[threadIdx.x] = acc[e];
        __syncthreads();
        for (int off = 128; off > 0; off >>= 1) {
            if (threadIdx.x < off) sred[threadIdx.x] += sred[threadIdx.x + off];
            __syncthreads();
        }
        if (threadIdx.x == 0) slogit[e] = sred[0];
        __syncthreads();
    }
    if (threadIdx.x == 0) {
        float m = slogit[0];
#pragma unroll
        for (int e = 1; e < EE; e++) m = fmaxf(m, slogit[e]);
        float p[EE], sum = 0.f;
#pragma unroll
        for (int e = 0; e < EE; e++) { p[e] = expf(slogit[e] - m); sum += p[e]; }
        float inv = 1.f / sum;
#pragma unroll
        for (int e = 0; e < EE; e++)
            g_probs[((size_t)(b * EE + e)) * SS + s] = p[e] * inv;
    }
}

// ---------------- top-k ----------------
__global__ __launch_bounds__(512) void topk_kernel() {
    const int be = blockIdx.x;
    __shared__ float v[SS];
    __shared__ int   ix[SS];
    for (int i = threadIdx.x; i < SS; i += 512) {
        v[i]  = g_probs[(size_t)be * SS + i];
        ix[i] = i;
    }
    __syncthreads();
    for (int ksz = 2; ksz <= SS; ksz <<= 1) {
        for (int j = ksz >> 1; j > 0; j >>= 1) {
            const int t = threadIdx.x;
            const int i = ((t & ~(j - 1)) << 1) | (t & (j - 1));
            const int p = i | j;
            const bool up = ((i & ksz) == 0);
            float vi = v[i], vp = v[p];
            int   xi = ix[i], xp = ix[p];
            bool i_better = (vi > vp) || (vi == vp && xi < xp);
            bool do_swap = up ? (!i_better) : i_better;
            if (do_swap) { v[i] = vp; v[p] = vi; ix[i] = xp; ix[p] = xi; }
            __syncthreads();
        }
    }
    for (int i = threadIdx.x; i < KTOK; i += 512) {
        g_G[(size_t)be * KTOK + i] = v[i];
        g_I[(size_t)be * KTOK + i] = ix[i];
    }
}

// ---------------- weight conversion ----------------
// w1[e][d][f] -> B-type (n=f, k=d, KT=DD)
__global__ __launch_bounds__(256) void convw1_kernel(const float* __restrict__ w1) {
    __shared__ float tile[32][33];
    const int e = blockIdx.z, d0 = blockIdx.y * 32, f0 = blockIdx.x * 32;
    const int tx = threadIdx.x, ty = threadIdx.y;
    const float* src = w1 + (size_t)e * DD * FF;
#pragma unroll
    for (int j = 0; j < 32; j += 8)
        tile[ty + j][tx] = src[(size_t)(d0 + ty + j) * FF + f0 + tx];
    __syncthreads();
    const size_t ebase = (size_t)e * (FF * DD / 2);
    const int tt = ty * 32 + tx;
#pragma unroll
    for (int it = 0; it < 2; it++) {
        int u = tt + it * 256;
        int fl = u >> 4, dp = u & 15;
        int n = f0 + fl;
        int k = d0 + 2 * dp;
        float v0 = tile[2 * dp][fl], v1 = tile[2 * dp + 1][fl];
        __nv_bfloat16 h0, l0, h1, l1;
        split_bf16(v0, h0, l0); split_bf16(v1, h1, l1);
        size_t w = ebase + ((size_t)(n >> 3) * (DD >> 5) + (k >> 5)) * 128
                 + ((n & 7) * 4 + ((k & 7) >> 1)) * 4
                 + ((k >> 4) & 1) * 2 + ((k >> 3) & 1);
        g_w1t_hi[w] = pack2(h0, h1);
        g_w1t_lo[w] = pack2(l0, l1);
    }
}

// w2[e][f][d] -> B-type (n=d, k=f, KT=FF)
__global__ __launch_bounds__(256) void convw2_kernel(const float* __restrict__ w2) {
    __shared__ float tile[32][33];
    const int e = blockIdx.z, f0 = blockIdx.y * 32, d0 = blockIdx.x * 32;
    const int tx = threadIdx.x, ty = threadIdx.y;
    const float* src = w2 + (size_t)e * FF * DD;
#pragma unroll
    for (int j = 0; j < 32; j += 8)
        tile[ty + j][tx] = src[(size_t)(f0 + ty + j) * DD + d0 + tx];
    __syncthreads();
    const size_t ebase = (size_t)e * (DD * FF / 2);
    const int tt = ty * 32 + tx;
#pragma unroll
    for (int it = 0; it < 2; it++) {
        int u = tt + it * 256;
        int dl = u >> 4, fp = u & 15;
        int n = d0 + dl;
        int k = f0 + 2 * fp;
        float v0 = tile[2 * fp][dl], v1 = tile[2 * fp + 1][dl];
        __nv_bfloat16 h0, l0, h1, l1;
        split_bf16(v0, h0, l0); split_bf16(v1, h1, l1);
        size_t w = ebase + ((size_t)(n >> 3) * (FF >> 5) + (k >> 5)) * 128
                 + ((n & 7) * 4 + ((k & 7) >> 1)) * 4
                 + ((k >> 4) & 1) * 2 + ((k >> 3) & 1);
        g_w2t_hi[w] = pack2(h0, h1);
        g_w2t_lo[w] = pack2(l0, l1);
    }
}

// ---------------- gather x -> A-type (KT=DD) ----------------
__global__ __launch_bounds__(256) void gatherx_kernel(const float* __restrict__ x) {
    const int berow = blockIdx.x;
    const int be = berow >> 8;
    const int m  = berow & 255;
    const int b  = be >> 3;
    const int tok = g_I[(size_t)be * KTOK + m];
    const float4* src = (const float4*)(x + ((size_t)b * SS + tok) * DD);
    float4 v = src[threadIdx.x];
    const size_t bbase = (size_t)be * (KTOK * DD / 2);
#pragma unroll
    for (int p = 0; p < 2; p++) {
        int k = threadIdx.x * 4 + p * 2;
        float e0 = p ? v.z : v.x;
        float e1 = p ? v.w : v.y;
        __nv_bfloat16 h0, l0, h1, l1;
        split_bf16(e0, h0, l0); split_bf16(e1, h1, l1);
        size_t w = bbase + ((size_t)(m >> 4) * (DD >> 4) + (k >> 4)) * 128
                 + ((m & 7) * 4 + ((k & 7) >> 1)) * 4
                 + ((m >> 3) & 1) + 2 * ((k >> 3) & 1);
        g_xg_hi[w] = pack2(h0, h1);
        g_xg_lo[w] = pack2(l0, l1);
    }
}

// ---------------- GEMM machinery ----------------
// Stage bytes: Ah [0,8K) Al [8K,16K) Bh [16K,24K) Bl [24K,32K)
#define STAGE_BYTES 32768
#define SMEM_DYN (3 * STAGE_BYTES)

__device__ __forceinline__ void load_stage(
    uint32_t smu,
    const uint32_t* __restrict__ aHi, const uint32_t* __restrict__ aLo,
    const uint32_t* __restrict__ bHi, const uint32_t* __restrict__ bLo,
    size_t aW, size_t bW, int stage, int mtStrideW, int ntStrideW, int tid)
{
    const int kt0 = stage * 2;
#pragma unroll
    for (int i = 0; i < 2; i++) {
        int c = tid + i * 256;
        size_t gw = aW + (size_t)(c >> 6) * mtStrideW
                  + (size_t)(kt0 + ((c >> 5) & 1)) * 128 + (c & 31) * 4;
        uint32_t ds = smu + c * 16;
        CP16(ds,        (const char*)(aHi + gw));
        CP16(ds + 8192, (const char*)(aLo + gw));
    }
#pragma unroll
    for (int i = 0; i < 2; i++) {
        int c = tid + i * 256;
        size_t gw = bW + (size_t)(c >> 5) * ntStrideW
                  + (size_t)stage * 128 + (c & 31) * 4;
        uint32_t ds = smu + 16384 + c * 16;
        CP16(ds,        (const char*)(bHi + gw));
        CP16(ds + 8192, (const char*)(bLo + gw));
    }
}

__device__ __forceinline__ void compute_stage(const char* st, int wm, int wn,
                                              int lane, float acc[2][8][4])
{
    uint4 Ah[2][2], Al[2][2];
#pragma unroll
    for (int mt = 0; mt < 2; mt++)
#pragma unroll
        for (int kt = 0; kt < 2; kt++) {
            int off = ((2 * wm + mt) * 2 + kt) * 512 + lane * 16;
            Ah[mt][kt] = *(const uint4*)(st + off);
            Al[mt][kt] = *(const uint4*)(st + 8192 + off);
        }
#pragma unroll
    for (int nt = 0; nt < 8; nt++) {
        int boff = (wn * 8 + nt) * 512 + lane * 16;
        uint4 Bh = *(const uint4*)(st + 16384 + boff);
        uint4 Bl = *(const uint4*)(st + 24576 + boff);
#pragma unroll
        for (int kt = 0; kt < 2; kt++) {
            uint32_t bh[2], bl[2];
            bh[0] = kt ? Bh.z : Bh.x;  bh[1] = kt ? Bh.w : Bh.y;
            bl[0] = kt ? Bl.z : Bl.x;  bl[1] = kt ? Bl.w : Bl.y;
#pragma unroll
            for (int mt = 0; mt < 2; mt++) {
                mma16816(acc[mt][nt], (const uint32_t*)&Ah[mt][kt], bh);
                mma16816(acc[mt][nt], (const uint32_t*)&Ah[mt][kt], bl);
                mma16816(acc[mt][nt], (const uint32_t*)&Al[mt][kt], bh);
            }
        }
    }
}

__device__ __forceinline__ void gemm_mainloop(
    const uint32_t* aHi, const uint32_t* aLo, const uint32_t* bHi, const uint32_t* bLo,
    size_t aW, size_t bW, int NT, int mtStrideW, int ntStrideW,
    char* smem, int tid, int wm, int wn, int lane, float acc[2][8][4])
{
    uint32_t smu = smem_u32(smem);
    load_stage(smu,               aHi, aLo, bHi, bLo, aW, bW, 0, mtStrideW, ntStrideW, tid);
    CP_COMMIT();
    load_stage(smu + STAGE_BYTES, aHi, aLo, bHi, bLo, aW, bW, 1, mtStrideW, ntStrideW, tid);
    CP_COMMIT();
    int buf = 0, nxt = 2;
    for (int s = 0; s < NT; s++) {
        asm volatile("cp.async.wait_group 1;" ::: "memory");
        __syncthreads();
        if (s + 2 < NT)
            load_stage(smu + nxt * STAGE_BYTES, aHi, aLo, bHi, bLo, aW, bW,
                       s + 2, mtStrideW, ntStrideW, tid);
        CP_COMMIT();
        compute_stage(smem + buf * STAGE_BYTES, wm, wn, lane, acc);
        buf = (buf + 1 == 3) ? 0 : buf + 1;
        nxt = (nxt + 1 == 3) ? 0 : nxt + 1;
    }
}

// ---------------- GEMM1 ----------------
__global__ __launch_bounds__(256, 2) void gemm1_tc() {
    const int be = blockIdx.z, e = be & 7;
    const int rowTile = blockIdx.y * 128;
    const int colTile = blockIdx.x * 128;
    extern __shared__ char smem[];
    const int tid = threadIdx.x, warp = tid >> 5, lane = tid & 31;
    const int wm = warp >> 1, wn = warp & 1;

    const size_t aW = (size_t)be * (KTOK * DD / 2) + (size_t)(rowTile >> 4) * 8192;
    const size_t bW = (size_t)e * (FF * DD / 2) + (size_t)(colTile >> 3) * 4096;

    float acc[2][8][4];
#pragma unroll
    for (int i = 0; i < 2; i++)
#pragma unroll
        for (int j = 0; j < 8; j++)
#pragma unroll
            for (int r = 0; r < 4; r++) acc[i][j][r] = 0.f;

    gemm_mainloop(g_xg_hi, g_xg_lo, g_w1t_hi, g_w1t_lo, aW, bW,
                  DD / 32, 8192, 4096, smem, tid, wm, wn, lane, acc);

    const size_t hBase = (size_t)be * (KTOK * FF / 2);
#pragma unroll
    for (int mt = 0; mt < 2; mt++) {
#pragma unroll
        for (int nt = 0; nt < 8; nt++) {
            int f = colTile + wn * 64 + nt * 8 + (lane & 3) * 2;
#pragma unroll
            for (int ph = 0; ph < 2; ph++) {
                int m = rowTile + wm * 32 + mt * 16 + (lane >> 2) + ph * 8;
                float v0 = acc[mt][nt][ph * 2 + 0];
                float v1 = acc[mt][nt][ph * 2 + 1];
                float s0 = v0 / (1.f + __expf(-v0));
                float s1 = v1 / (1.f + __expf(-v1));
                __nv_bfloat16 h0, l0, h1, l1;
                split_bf16(s0, h0, l0); split_bf16(s1, h1, l1);
                size_t w = hBase + ((size_t)(m >> 4) * (FF >> 4) + (f >> 4)) * 128
                         + ((m & 7) * 4 + ((f & 7) >> 1)) * 4
                         + ((m >> 3) & 1) + 2 * ((f >> 3) & 1);
                g_h_hi[w] = pack2(h0, h1);
                g_h_lo[w] = pack2(l0, l1);
            }
        }
    }
}

// ---------------- GEMM2 ----------------
__global__ __launch_bounds__(256, 2) void gemm2_tc(float* __restrict__ out) {
    const int be = blockIdx.z, e = be & 7, b = be >> 3;
    const int rowTile = blockIdx.y * 128;
    const int colTile = blockIdx.x * 128;
    extern __shared__ char smem[];
    const int tid = threadIdx.x, warp = tid >> 5, lane = tid & 31;
    const int wm = warp >> 1, wn = warp & 1;

    const size_t aW = (size_t)be * (KTOK * FF / 2) + (size_t)(rowTile >> 4) * 16384;
    const size_t bW = (size_t)e * (DD * FF / 2) + (size_t)(colTile >> 3) * 8192;

    float acc[2][8][4];
#pragma unroll
    for (int i = 0; i < 2; i++)
#pragma unroll
        for (int j = 0; j < 8; j++)
#pragma unroll
            for (int r = 0; r < 4; r++) acc[i][j][r] = 0.f;

    gemm_mainloop(g_h_hi, g_h_lo, g_w2t_hi, g_w2t_lo, aW, bW,
                  FF / 32, 16384, 8192, smem, tid, wm, wn, lane, acc);

    __shared__ int   s_tok[128];
    __shared__ float s_gate[128];
    if (tid < 128) {
        size_t idx = (size_t)be * KTOK + rowTile + tid;
        s_tok[tid]  = g_I[idx];
        s_gate[tid] = g_G[idx];
    }
    __syncthreads();

#pragma unroll
    for (int mt = 0; mt < 2; mt++) {
#pragma unroll
        for (int nt = 0; nt < 8; nt++) {
            int d = colTile + wn * 64 + nt * 8 + (lane & 3) * 2;
#pragma unroll
            for (int ph = 0; ph < 2; ph++) {
                int rloc = wm * 32 + mt * 16 + (lane >> 2) + ph * 8;
                int tok = s_tok[rloc];
                float gate = s_gate[rloc];
                float* op = out + ((size_t)b * SS + tok) * DD + d;
                atomicAdd(op,     gate * acc[mt][nt][ph * 2 + 0]);
                atomicAdd(op + 1, gate * acc[mt][nt][ph * 2 + 1]);
            }
        }
    }
}

// ---------------- launcher ----------------
extern "C" void kernel_launch(void* const* d_in, const int* in_sizes, int n_in,
                              void* d_out, int out_size) {
    const float* x  = (const float*)d_in[0];
    const float* cw = (const float*)d_in[1];
    const float* w1 = (const float*)d_in[2];
    const float* w2 = (const float*)d_in[3];
    float* out = (float*)d_out;

    cudaFuncSetAttribute(gemm1_tc, cudaFuncAttributeMaxDynamicSharedMemorySize, SMEM_DYN);
    cudaFuncSetAttribute(gemm2_tc, cudaFuncAttributeMaxDynamicSharedMemorySize, SMEM_DYN);

    cudaMemsetAsync(out, 0, (size_t)BB * SS * DD * sizeof(float), 0);

    router_kernel<<<BB * SS, 256>>>(x, cw);
    topk_kernel<<<NBE, 512>>>();

    convw1_kernel<<<dim3(FF / 32, DD / 32, EE), dim3(32, 8)>>>(w1);
    convw2_kernel<<<dim3(DD / 32, FF / 32, EE), dim3(32, 8)>>>(w2);
    gatherx_kernel<<<NBE * KTOK, 256>>>(x);

    gemm1_tc<<<dim3(FF / 128, KTOK / 128, NBE), 256, SMEM_DYN>>>();
    gemm2_tc<<<dim3(DD / 128, KTOK / 128, NBE), 256, SMEM_DYN>>>(out);
}